// round 12
// baseline (speedup 1.0000x reference)
#include <cuda_runtime.h>
#include <cuda_fp16.h>
#include <cstdint>

// ---------------- problem constants ----------------
#define B_SZ 512
#define D_SZ 256
#define C_SZ 100000
#define C_PAD 100096              // 782 * 128
#define NCHB 782                  // class chunks of 128
#define MARGIN 0.2f
#define SCALE  30.0f
#define SHIFT  30.0f              // fixed LSE shift: logits <= S = 30
#define WPREP_BLOCKS 6250         // 16 classes per block (4 per warp, 128 thr)
#define GEMM_BLOCKS  (4 * NCHB)   // 3128
#define TOTAL_BLOCKS (WPREP_BLOCKS + B_SZ + GEMM_BLOCKS)

// GEMM smem: 4 stages x (A 8KB + B 8KB) = 64KB, + 1KB reduce buffer
#define STAGE_BYTES 16384
#define RBUF_OFF    65536
#define GEMM_SMEM   (65536 + 1024)

// control block layout (all reset by one memset per call)
#define CTRL_WCNT   0             // [0..781]   per-chunk W-ready counters
#define CTRL_XCNT   782           // x-ready counter
#define CTRL_DONE   783           // row_kernel completion counter
#define CTRL_ROWSUM 784           // [784..1295] per-row exp-sums (float bits)
#define CTRL_WORDS  (784 + B_SZ)

// ---------------- device scratch (no runtime alloc) ----------------
__device__ __align__(16) __half g_wh[(size_t)C_PAD * D_SZ];  // l2norm(W) fp16; pad rows zero
__device__ __align__(16) __half g_xh[B_SZ * D_SZ];           // S * l2norm(x) fp16
__device__ unsigned g_ctrl[CTRL_WORDS];
__device__ float g_loss[B_SZ];

// ---------------- PTX helpers ----------------
__device__ __forceinline__ uint32_t smem_u32(const void* p) {
    uint32_t a;
    asm("{ .reg .u64 t; cvta.to.shared.u64 t, %1; cvt.u32.u64 %0, t; }" : "=r"(a) : "l"(p));
    return a;
}
#define CP_ASYNC16(dst, src) \
    asm volatile("cp.async.cg.shared.global [%0], [%1], 16;" :: "r"(dst), "l"(src) : "memory")
#define CP_COMMIT() asm volatile("cp.async.commit_group;" ::: "memory")
#define CP_WAIT(n)  asm volatile("cp.async.wait_group %0;" :: "n"(n) : "memory")

#define LDSM_X4(r0, r1, r2, r3, addr) \
    asm volatile("ldmatrix.sync.aligned.m8n8.x4.shared.b16 {%0,%1,%2,%3}, [%4];" \
        : "=r"(r0), "=r"(r1), "=r"(r2), "=r"(r3) : "r"(addr))

// fp16 in, fp16 accumulate: D(2x f16x2) = A(4) * B(2) + D
#define MMA_F16ACC(d0, d1, a0, a1, a2, a3, b0, b1) \
    asm volatile("mma.sync.aligned.m16n8k16.row.col.f16.f16.f16.f16 " \
        "{%0,%1}, {%2,%3,%4,%5}, {%6,%7}, {%0,%1};" \
        : "+r"(d0), "+r"(d1) \
        : "r"(a0), "r"(a1), "r"(a2), "r"(a3), "r"(b0), "r"(b1))

// ---------------- fused kernel: W/x prep producers + HMMA GEMM consumers ----------------
// 128 threads per block, dynamic smem GEMM_SMEM.
__global__ void __launch_bounds__(128, 3)
fused_kernel(const float* __restrict__ w, const float* __restrict__ x) {
    extern __shared__ __align__(1024) char smem[];
    const int bid = blockIdx.x;
    const int tid = threadIdx.x, lane = tid & 31, wid = tid >> 5;

    // ================= W prep =================
    if (bid < WPREP_BLOCKS) {
        int cls0 = bid * 16 + wid * 4;
        float4 v[4][2];
        #pragma unroll
        for (int q = 0; q < 4; q++) {
            const float4* wr = (const float4*)(w + (size_t)(cls0 + q) * D_SZ);
            v[q][0] = wr[lane];
            v[q][1] = wr[lane + 32];
        }
        float s[4];
        #pragma unroll
        for (int q = 0; q < 4; q++) {
            float4 a = v[q][0], b = v[q][1];
            s[q] = a.x*a.x + a.y*a.y + a.z*a.z + a.w*a.w
                 + b.x*b.x + b.y*b.y + b.z*b.z + b.w*b.w;
        }
        #pragma unroll
        for (int m = 16; m; m >>= 1)
            #pragma unroll
            for (int q = 0; q < 4; q++)
                s[q] += __shfl_xor_sync(0xffffffffu, s[q], m);
        #pragma unroll
        for (int q = 0; q < 4; q++) {
            float inv = 1.0f / fmaxf(sqrtf(s[q]), 1e-12f);
            float4 a = v[q][0], b = v[q][1];
            __half2* o = (__half2*)(g_wh + (size_t)(cls0 + q) * D_SZ);
            o[2*lane]        = __floats2half2_rn(a.x * inv, a.y * inv);
            o[2*lane + 1]    = __floats2half2_rn(a.z * inv, a.w * inv);
            o[64 + 2*lane]   = __floats2half2_rn(b.x * inv, b.y * inv);
            o[64 + 2*lane+1] = __floats2half2_rn(b.z * inv, b.w * inv);
        }
        __syncthreads();
        __threadfence();
        if (tid == 0) atomicAdd(&g_ctrl[CTRL_WCNT + (bid >> 3)], 1u);   // 16 classes within one 128-chunk
        return;
    }

    // ================= x prep =================
    if (bid < WPREP_BLOCKS + B_SZ) {
        int b = bid - WPREP_BLOCKS;            // 128 threads, 2 d-values each
        float2 v = *(const float2*)(x + b * D_SZ + tid * 2);
        float s = v.x * v.x + v.y * v.y;
        #pragma unroll
        for (int m = 16; m; m >>= 1) s += __shfl_xor_sync(0xffffffffu, s, m);
        float* ws = (float*)smem;
        if (lane == 0) ws[wid] = s;
        __syncthreads();
        float tot = ws[0] + ws[1] + ws[2] + ws[3];
        float inv = 1.0f / fmaxf(sqrtf(tot), 1e-12f);
        *(__half2*)(g_xh + b * D_SZ + tid * 2) =
            __floats2half2_rn(SCALE * v.x * inv, SCALE * v.y * inv);
        __syncthreads();
        __threadfence();
        if (tid == 0) atomicAdd(&g_ctrl[CTRL_XCNT], 1u);
        return;
    }

    // ================= GEMM consumer =================
    const int g = bid - (WPREP_BLOCKS + B_SZ);
    const int chunk = g >> 2, c0 = chunk * 128, b0 = (g & 3) * 128;
    const uint32_t sb = smem_u32(smem);
    const int wm = wid >> 1, wn = wid & 1;            // warp grid 2 x 2

    // wait for producers (x fully; this W chunk)
    if (tid == 0) {
        const unsigned wtarget = (chunk == NCHB - 1) ? 2u : 8u;
        volatile unsigned* xc = &g_ctrl[CTRL_XCNT];
        volatile unsigned* wc = &g_ctrl[CTRL_WCNT + chunk];
        while (*xc < (unsigned)B_SZ) __nanosleep(200);
        while (*wc < wtarget)        __nanosleep(200);
    }
    __syncthreads();
    __threadfence();   // acquire: order flag read before tile reads

    // ---- cp.async producer: 4 A-chunks + 4 B-chunks of 16B per thread ----
    uint32_t swz[4];
    const __half *gA[4], *gB[4];
    #pragma unroll
    for (int i = 0; i < 4; i++) {
        int f = tid + 128 * i;                // 16B chunk id in 128x32 tile
        int row = f >> 2, c16 = f & 3;
        swz[i] = (uint32_t)row * 64 + ((uint32_t)(c16 ^ ((row >> 1) & 3)) << 4);
        gA[i] = g_xh + (size_t)(b0 + row) * D_SZ + c16 * 8;
        gB[i] = g_wh + (size_t)(c0 + row) * D_SZ + c16 * 8;
    }

    auto load_stage = [&](int kt) {
        uint32_t abase = sb + (kt & 3) * STAGE_BYTES;
        uint32_t bbase = abase + 8192;
        #pragma unroll
        for (int i = 0; i < 4; i++) CP_ASYNC16(abase + swz[i], gA[i] + kt * 32);
        #pragma unroll
        for (int i = 0; i < 4; i++) CP_ASYNC16(bbase + swz[i], gB[i] + kt * 32);
        CP_COMMIT();
    };

    // ---- ldmatrix consumer indexing ----
    const int rA = wm * 64 + (lane & 15);
    const uint32_t aoff = (uint32_t)rA * 64;
    const int saN = (rA >> 1) & 3;
    const int cA = lane >> 4;
    const int rB = wn * 64 + ((lane >> 4) << 3) + (lane & 7);
    const uint32_t boff = (uint32_t)rB * 64;
    const int sbN = (rB >> 1) & 3;
    const int cB = (lane >> 3) & 1;

    uint32_t acc[4][8][2];                 // f16x2 accumulators, 64 regs
    #pragma unroll
    for (int i = 0; i < 4; i++)
        #pragma unroll
        for (int j = 0; j < 8; j++) { acc[i][j][0] = 0u; acc[i][j][1] = 0u; }

    auto compute_stage = [&](int st) {
        uint32_t aBase = sb + st * STAGE_BYTES;
        uint32_t bBase = aBase + 8192;
        #pragma unroll
        for (int s = 0; s < 2; s++) {                 // two k16 steps per BK=32
            uint32_t a_[4][4], b_[4][4];
            #pragma unroll
            for (int mt = 0; mt < 4; mt++) {
                uint32_t ad = aBase + aoff + mt * 1024 +
                              ((uint32_t)((s * 2 + cA) ^ saN) << 4);
                LDSM_X4(a_[mt][0], a_[mt][1], a_[mt][2], a_[mt][3], ad);
            }
            #pragma unroll
            for (int jp = 0; jp < 4; jp++) {
                uint32_t bd = bBase + boff + jp * 1024 +
                              ((uint32_t)((s * 2 + cB) ^ sbN) << 4);
                LDSM_X4(b_[jp][0], b_[jp][1], b_[jp][2], b_[jp][3], bd);
            }
            #pragma unroll
            for (int mt = 0; mt < 4; mt++)
                #pragma unroll
                for (int nt = 0; nt < 8; nt++) {
                    int jp = nt >> 1, hb = (nt & 1) * 2;
                    MMA_F16ACC(acc[mt][nt][0], acc[mt][nt][1],
                               a_[mt][0], a_[mt][1], a_[mt][2], a_[mt][3],
                               b_[jp][hb], b_[jp][hb + 1]);
                }
        }
    };

    // ---- pipeline: 8 K-stages, 4 buffers, 3 in flight ----
    load_stage(0); load_stage(1); load_stage(2);
    #pragma unroll 1
    for (int kt = 0; kt < 5; kt++) {
        CP_WAIT(2); __syncthreads();
        compute_stage(kt & 3);
        load_stage(kt + 3);
    }
    CP_WAIT(2); __syncthreads(); compute_stage(1);
    CP_WAIT(1); __syncthreads(); compute_stage(2);
    CP_WAIT(0); __syncthreads(); compute_stage(3);

    // ---- epilogue: per-row sum of exp(v - SHIFT), one atomic per row ----
    const bool edge = (c0 + 128 > C_SZ);
    float es[4][2];
    #pragma unroll
    for (int mt = 0; mt < 4; mt++) { es[mt][0] = 0.f; es[mt][1] = 0.f; }
    #pragma unroll
    for (int mt = 0; mt < 4; mt++)
        #pragma unroll
        for (int nt = 0; nt < 8; nt++) {
            int cgb = c0 + wn * 64 + nt * 8 + (lane & 3) * 2;
            #pragma unroll
            for (int h = 0; h < 2; h++) {
                float2 v = __half22float2(*(__half2*)&acc[mt][nt][h]);
                float t0 = __expf(v.x - SHIFT);
                float t1 = __expf(v.y - SHIFT);
                if (edge && (cgb + 0 >= C_SZ)) t0 = 0.f;
                if (edge && (cgb + 1 >= C_SZ)) t1 = 0.f;
                es[mt][h] += t0 + t1;
            }
        }
    #pragma unroll
    for (int m = 1; m <= 2; m <<= 1)
        #pragma unroll
        for (int mt = 0; mt < 4; mt++) {
            es[mt][0] += __shfl_xor_sync(0xffffffffu, es[mt][0], m);
            es[mt][1] += __shfl_xor_sync(0xffffffffu, es[mt][1], m);
        }

    float* rbuf = (float*)(smem + RBUF_OFF);          // [2 wm][2 wn][64 rows]
    if ((lane & 3) == 0) {
        int rl = lane >> 2;
        #pragma unroll
        for (int mt = 0; mt < 4; mt++) {
            rbuf[(wm * 2 + wn) * 64 + mt * 16 + rl]     = es[mt][0];
            rbuf[(wm * 2 + wn) * 64 + mt * 16 + 8 + rl] = es[mt][1];
        }
    }
    __syncthreads();
    {
        int wmx = tid >> 6, rl = tid & 63;
        float s = rbuf[(wmx * 2 + 0) * 64 + rl] + rbuf[(wmx * 2 + 1) * 64 + rl];
        atomicAdd((float*)&g_ctrl[CTRL_ROWSUM + b0 + tid], s);
    }
}

// ---------------- kernel 2: per-row specials + loss + fused final (128 threads) ----------------
__global__ void row_kernel(const float* __restrict__ lamp,
                           const int* __restrict__ t1, const int* __restrict__ p1,
                           const int* __restrict__ t2, const int* __restrict__ p2,
                           float* __restrict__ out) {
    int b = blockIdx.x;
    int tid = threadIdx.x, wid = tid >> 5, lane = tid & 31;

    __shared__ float sv[4], svraw[4];
    __shared__ int   sidx[4];
    __shared__ float ss[128];
    __shared__ bool  lastb;

    int i0 = t1[b], i1 = p1[b], i2 = t2[b], i3 = p2[b];

    {
        int qi = (wid == 0) ? i0 : (wid == 1) ? i1 : (wid == 2) ? i2 : i3;
        const uint4* xr = (const uint4*)(g_xh + (size_t)b * D_SZ);
        const uint4* wr = (const uint4*)(g_wh + (size_t)qi * D_SZ);
        uint4 xv = xr[lane], wv = wr[lane];   // 8 fp16 each
        float s = 0.f;
        const uint32_t* xu = (const uint32_t*)&xv;
        const uint32_t* wu = (const uint32_t*)&wv;
        #pragma unroll
        for (int i = 0; i < 4; i++) {
            float2 xf = __half22float2(*(const __half2*)&xu[i]);
            float2 wf = __half22float2(*(const __half2*)&wu[i]);
            s += xf.x * wf.x + xf.y * wf.y;
        }
        #pragma unroll
        for (int m = 16; m; m >>= 1) s += __shfl_xor_sync(0xffffffffu, s, m);
        if (lane == 0) {
            float raw = s;                               // ~= what the GEMM summed
            float val = raw;
            if (qi == i0) val = raw - SCALE * MARGIN;    // pre-scale scatter
            if (qi == i1) val = raw / SCALE - MARGIN;    // post-scale scatters
            if (qi == i2) val = raw / SCALE - MARGIN;
            if (qi == i3) val = raw / SCALE - MARGIN;    // last write wins
            svraw[wid] = raw;
            sv[wid] = val;
            sidx[wid] = qi;
        }
    }
    __syncthreads();

    if (tid == 0) {
        float S0 = *(float*)&g_ctrl[CTRL_ROWSUM + b];
        #pragma unroll
        for (int q = 0; q < 3; q++) {
            bool lastq = true;
            #pragma unroll
            for (int r = q + 1; r < 4; r++) if (sidx[r] == sidx[q]) lastq = false;
            if (lastq) S0 += __expf(sv[q] - SHIFT) - __expf(svraw[q] - SHIFT);
        }
        S0 += __expf(sv[3] - SHIFT) - __expf(svraw[3] - SHIFT);
        float lz = SHIFT + logf(S0);
        float lam = *lamp;
        g_loss[b] = lam * (0.2f * (lz - sv[0]) + 0.8f * (lz - sv[1]))
                  + (1.f - lam) * (0.2f * (lz - sv[2]) + 0.8f * (lz - sv[3]));
        __threadfence();
        lastb = (atomicAdd(&g_ctrl[CTRL_DONE], 1u) == B_SZ - 1);
    }
    __syncthreads();

    if (lastb) {   // deterministic final reduction by the last-arriving block
        float r = 0.f;
        for (int i = tid; i < B_SZ; i += 128) r += __ldcg(&g_loss[i]);
        ss[tid] = r;
        __syncthreads();
        for (int st = 64; st; st >>= 1) {
            if (tid < st) ss[tid] += ss[tid + st];
            __syncthreads();
        }
        if (tid == 0) out[0] = ss[0] / (float)B_SZ;
    }
}

// ---------------- host launch ----------------
extern "C" void kernel_launch(void* const* d_in, const int* in_sizes, int n_in,
                              void* d_out, int out_size) {
    const float* x   = (const float*)d_in[0];
    const float* w   = (const float*)d_in[1];
    const float* lam = (const float*)d_in[2];
    const int* t1    = (const int*)d_in[3];
    const int* p1    = (const int*)d_in[4];
    const int* t2    = (const int*)d_in[5];
    const int* p2    = (const int*)d_in[6];
    float* out = (float*)d_out;

    static void* ctrl_ptr = nullptr;
    static bool init_done = false;
    if (!init_done) {
        cudaFuncSetAttribute(fused_kernel,
                             cudaFuncAttributeMaxDynamicSharedMemorySize, GEMM_SMEM);
        cudaGetSymbolAddress(&ctrl_ptr, g_ctrl);
        init_done = true;
    }

    cudaMemsetAsync(ctrl_ptr, 0, CTRL_WORDS * sizeof(unsigned));   // capture-safe reset
    fused_kernel<<<TOTAL_BLOCKS, 128, GEMM_SMEM>>>(w, x);
    row_kernel<<<B_SZ, 128>>>(lam, t1, p1, t2, p2, out);
}

// round 13
// speedup vs baseline: 1.2051x; 1.2051x over previous
#include <cuda_runtime.h>
#include <cuda_fp16.h>
#include <cstdint>

// ---------------- problem constants ----------------
#define B_SZ 512
#define D_SZ 256
#define C_SZ 100000
#define C_PAD 100096              // 782 * 128
#define NCHB 782                  // class chunks of 128
#define MARGIN 0.2f
#define SCALE  30.0f
#define SHIFT  30.0f              // fixed LSE shift: logits <= S = 30
#define WCONV_BLOCKS 6250         // 16 classes per block (2 per warp)
#define PREP_BLOCKS (WCONV_BLOCKS + B_SZ + B_SZ)   // W conv + x conv + specials

// GEMM smem: 4 stages x (A 8KB + B 8KB) = 64KB, + 1KB reduce buffer
#define STAGE_BYTES 16384
#define RBUF_OFF    65536
#define GEMM_SMEM   (65536 + 1024)

// ---------------- device scratch (no runtime alloc) ----------------
__device__ __align__(16) __half g_wh[(size_t)C_PAD * D_SZ];  // l2norm(W) fp16; pad rows zero
__device__ __align__(16) __half g_xh[B_SZ * D_SZ];           // S * l2norm(x) fp16
__device__ float g_rowsum[B_SZ];                // per-row sum of exp(v - SHIFT), atomic
__device__ float g_sv[B_SZ * 4];                // post-scatter special values
__device__ float g_svraw[B_SZ * 4];             // raw S*cos at special indices (quantized ops)
__device__ int   g_sidx[B_SZ * 4];              // special indices

// ---------------- PTX helpers ----------------
__device__ __forceinline__ uint32_t smem_u32(const void* p) {
    uint32_t a;
    asm("{ .reg .u64 t; cvta.to.shared.u64 t, %1; cvt.u32.u64 %0, t; }" : "=r"(a) : "l"(p));
    return a;
}
#define CP_ASYNC16(dst, src) \
    asm volatile("cp.async.cg.shared.global [%0], [%1], 16;" :: "r"(dst), "l"(src) : "memory")
#define CP_COMMIT() asm volatile("cp.async.commit_group;" ::: "memory")
#define CP_WAIT(n)  asm volatile("cp.async.wait_group %0;" :: "n"(n) : "memory")

#define LDSM_X4(r0, r1, r2, r3, addr) \
    asm volatile("ldmatrix.sync.aligned.m8n8.x4.shared.b16 {%0,%1,%2,%3}, [%4];" \
        : "=r"(r0), "=r"(r1), "=r"(r2), "=r"(r3) : "r"(addr))

// fp16 in, fp16 accumulate: D(2x f16x2) = A(4) * B(2) + D
#define MMA_F16ACC(d0, d1, a0, a1, a2, a3, b0, b1) \
    asm volatile("mma.sync.aligned.m16n8k16.row.col.f16.f16.f16.f16 " \
        "{%0,%1}, {%2,%3,%4,%5}, {%6,%7}, {%0,%1};" \
        : "+r"(d0), "+r"(d1) \
        : "r"(a0), "r"(a1), "r"(a2), "r"(a3), "r"(b0), "r"(b1))

__device__ __forceinline__ float q16(float v) {   // quantize to fp16, back to fp32
    return __half2float(__float2half_rn(v));
}

// ---------------- kernel 1: fused prep (W conv | x conv | specials) ----------------
__global__ void prep_kernel(const float* __restrict__ w, const float* __restrict__ x,
                            const int* __restrict__ t1, const int* __restrict__ p1,
                            const int* __restrict__ t2, const int* __restrict__ p2) {
    int bid = blockIdx.x;
    if (bid < WCONV_BLOCKS) {
        // ---- W rows -> l2norm fp16, 16 classes/block, 2 per warp ----
        int cls0 = bid * 16 + (threadIdx.x >> 5) * 2;
        int lane = threadIdx.x & 31;
        const float4* w0r = (const float4*)(w + (size_t)cls0 * D_SZ);
        const float4* w1r = (const float4*)(w + (size_t)(cls0 + 1) * D_SZ);
        float4 a0 = w0r[lane], a1 = w0r[lane + 32];
        float4 b0 = w1r[lane], b1 = w1r[lane + 32];
        float sa = a0.x*a0.x + a0.y*a0.y + a0.z*a0.z + a0.w*a0.w
                 + a1.x*a1.x + a1.y*a1.y + a1.z*a1.z + a1.w*a1.w;
        float sb = b0.x*b0.x + b0.y*b0.y + b0.z*b0.z + b0.w*b0.w
                 + b1.x*b1.x + b1.y*b1.y + b1.z*b1.z + b1.w*b1.w;
        #pragma unroll
        for (int m = 16; m; m >>= 1) {
            sa += __shfl_xor_sync(0xffffffffu, sa, m);
            sb += __shfl_xor_sync(0xffffffffu, sb, m);
        }
        float ia = 1.0f / fmaxf(sqrtf(sa), 1e-12f);
        float ib = 1.0f / fmaxf(sqrtf(sb), 1e-12f);
        __half2* o0 = (__half2*)(g_wh + (size_t)cls0 * D_SZ);
        __half2* o1 = (__half2*)(g_wh + (size_t)(cls0 + 1) * D_SZ);
        o0[2*lane]        = __floats2half2_rn(a0.x * ia, a0.y * ia);
        o0[2*lane + 1]    = __floats2half2_rn(a0.z * ia, a0.w * ia);
        o0[64 + 2*lane]   = __floats2half2_rn(a1.x * ia, a1.y * ia);
        o0[64 + 2*lane+1] = __floats2half2_rn(a1.z * ia, a1.w * ia);
        o1[2*lane]        = __floats2half2_rn(b0.x * ib, b0.y * ib);
        o1[2*lane + 1]    = __floats2half2_rn(b0.z * ib, b0.w * ib);
        o1[64 + 2*lane]   = __floats2half2_rn(b1.x * ib, b1.y * ib);
        o1[64 + 2*lane+1] = __floats2half2_rn(b1.z * ib, b1.w * ib);
    } else if (bid < WCONV_BLOCKS + B_SZ) {
        // ---- x row -> S * l2norm(x) fp16 ----
        int b = bid - WCONV_BLOCKS, t = threadIdx.x;   // 256 threads
        if (t == 0) g_rowsum[b] = 0.f;                 // per-call reset (graph-replay safe)
        float v = x[b * D_SZ + t];
        float s = v * v;
        #pragma unroll
        for (int m = 16; m; m >>= 1) s += __shfl_xor_sync(0xffffffffu, s, m);
        __shared__ float ws[8];
        if ((t & 31) == 0) ws[t >> 5] = s;
        __syncthreads();
        __shared__ float inv;
        if (t == 0) {
            float tot = 0.f;
            #pragma unroll
            for (int i = 0; i < 8; i++) tot += ws[i];
            inv = 1.0f / fmaxf(sqrtf(tot), 1e-12f);
        }
        __syncthreads();
        g_xh[b * D_SZ + t] = __float2half_rn(SCALE * v * inv);
    } else {
        // ---- specials: 4 warps (of 8), one query each; inline quantization ----
        int b = bid - (WCONV_BLOCKS + B_SZ);
        int wid = threadIdx.x >> 5, lane = threadIdx.x & 31;
        if (wid >= 4) return;
        int i0 = t1[b], i1 = p1[b], i2 = t2[b], i3 = p2[b];
        int qi = (wid == 0) ? i0 : (wid == 1) ? i1 : (wid == 2) ? i2 : i3;

        const float4* xr = (const float4*)(x + (size_t)b * D_SZ);
        const float4* wr = (const float4*)(w + (size_t)qi * D_SZ);
        float4 x0 = xr[2*lane], x1 = xr[2*lane+1];
        float4 w0 = wr[2*lane], w1 = wr[2*lane+1];
        float sx = x0.x*x0.x + x0.y*x0.y + x0.z*x0.z + x0.w*x0.w
                 + x1.x*x1.x + x1.y*x1.y + x1.z*x1.z + x1.w*x1.w;
        float sw = w0.x*w0.x + w0.y*w0.y + w0.z*w0.z + w0.w*w0.w
                 + w1.x*w1.x + w1.y*w1.y + w1.z*w1.z + w1.w*w1.w;
        #pragma unroll
        for (int m = 16; m; m >>= 1) {
            sx += __shfl_xor_sync(0xffffffffu, sx, m);
            sw += __shfl_xor_sync(0xffffffffu, sw, m);
        }
        float ix = 1.0f / fmaxf(sqrtf(sx), 1e-12f);
        float iw = 1.0f / fmaxf(sqrtf(sw), 1e-12f);
        // quantized operands exactly as the GEMM sees them
        float xq[8] = {x0.x, x0.y, x0.z, x0.w, x1.x, x1.y, x1.z, x1.w};
        float wq[8] = {w0.x, w0.y, w0.z, w0.w, w1.x, w1.y, w1.z, w1.w};
        float s = 0.f;
        #pragma unroll
        for (int i = 0; i < 8; i++)
            s += q16(SCALE * xq[i] * ix) * q16(wq[i] * iw);
        #pragma unroll
        for (int m = 16; m; m >>= 1) s += __shfl_xor_sync(0xffffffffu, s, m);
        if (lane == 0) {
            float raw = s;                               // ~= what the GEMM sums
            float val = raw;
            if (qi == i0) val = raw - SCALE * MARGIN;    // pre-scale scatter
            if (qi == i1) val = raw / SCALE - MARGIN;    // post-scale scatters
            if (qi == i2) val = raw / SCALE - MARGIN;
            if (qi == i3) val = raw / SCALE - MARGIN;    // last write wins
            g_svraw[b * 4 + wid] = raw;
            g_sv[b * 4 + wid] = val;
            g_sidx[b * 4 + wid] = qi;
        }
    }
}

// ---------------- kernel 2: fp16 HMMA GEMM, 64x64 warp tiles (frozen) ----------------
// grid (4, 782). 128 threads = 4 warps (2m x 2n), warp tile 64m x 64n.
__global__ void __launch_bounds__(128, 3)
gemm_lse_kernel() {
    extern __shared__ __align__(1024) char smem[];
    const uint32_t sb = smem_u32(smem);
    const int tid = threadIdx.x, lane = tid & 31, wid = tid >> 5;
    const int wm = wid >> 1, wn = wid & 1;            // warp grid 2 x 2
    const int chunk = blockIdx.y, c0 = chunk * 128, b0 = blockIdx.x * 128;

    // ---- cp.async producer: 4 A-chunks + 4 B-chunks of 16B per thread ----
    uint32_t swz[4];
    const __half *gA[4], *gB[4];
    #pragma unroll
    for (int i = 0; i < 4; i++) {
        int f = tid + 128 * i;                // 16B chunk id in 128x32 tile
        int row = f >> 2, c16 = f & 3;
        swz[i] = (uint32_t)row * 64 + ((uint32_t)(c16 ^ ((row >> 1) & 3)) << 4);
        gA[i] = g_xh + (size_t)(b0 + row) * D_SZ + c16 * 8;
        gB[i] = g_wh + (size_t)(c0 + row) * D_SZ + c16 * 8;
    }

    auto load_stage = [&](int kt) {
        uint32_t abase = sb + (kt & 3) * STAGE_BYTES;
        uint32_t bbase = abase + 8192;
        #pragma unroll
        for (int i = 0; i < 4; i++) CP_ASYNC16(abase + swz[i], gA[i] + kt * 32);
        #pragma unroll
        for (int i = 0; i < 4; i++) CP_ASYNC16(bbase + swz[i], gB[i] + kt * 32);
        CP_COMMIT();
    };

    // ---- ldmatrix consumer indexing ----
    const int rA = wm * 64 + (lane & 15);
    const uint32_t aoff = (uint32_t)rA * 64;
    const int saN = (rA >> 1) & 3;
    const int cA = lane >> 4;
    const int rB = wn * 64 + ((lane >> 4) << 3) + (lane & 7);
    const uint32_t boff = (uint32_t)rB * 64;
    const int sbN = (rB >> 1) & 3;
    const int cB = (lane >> 3) & 1;

    uint32_t acc[4][8][2];                 // f16x2 accumulators, 64 regs
    #pragma unroll
    for (int i = 0; i < 4; i++)
        #pragma unroll
        for (int j = 0; j < 8; j++) { acc[i][j][0] = 0u; acc[i][j][1] = 0u; }

    auto compute_stage = [&](int st) {
        uint32_t aBase = sb + st * STAGE_BYTES;
        uint32_t bBase = aBase + 8192;
        #pragma unroll
        for (int s = 0; s < 2; s++) {                 // two k16 steps per BK=32
            uint32_t a_[4][4], b_[4][4];
            #pragma unroll
            for (int mt = 0; mt < 4; mt++) {
                uint32_t ad = aBase + aoff + mt * 1024 +
                              ((uint32_t)((s * 2 + cA) ^ saN) << 4);
                LDSM_X4(a_[mt][0], a_[mt][1], a_[mt][2], a_[mt][3], ad);
            }
            #pragma unroll
            for (int jp = 0; jp < 4; jp++) {
                uint32_t bd = bBase + boff + jp * 1024 +
                              ((uint32_t)((s * 2 + cB) ^ sbN) << 4);
                LDSM_X4(b_[jp][0], b_[jp][1], b_[jp][2], b_[jp][3], bd);
            }
            #pragma unroll
            for (int mt = 0; mt < 4; mt++)
                #pragma unroll
                for (int nt = 0; nt < 8; nt++) {
                    int jp = nt >> 1, hb = (nt & 1) * 2;
                    MMA_F16ACC(acc[mt][nt][0], acc[mt][nt][1],
                               a_[mt][0], a_[mt][1], a_[mt][2], a_[mt][3],
                               b_[jp][hb], b_[jp][hb + 1]);
                }
        }
    };

    // ---- pipeline: 8 K-stages, 4 buffers, 3 in flight ----
    load_stage(0); load_stage(1); load_stage(2);
    #pragma unroll 1
    for (int kt = 0; kt < 5; kt++) {
        CP_WAIT(2); __syncthreads();
        compute_stage(kt & 3);
        load_stage(kt + 3);
    }
    CP_WAIT(2); __syncthreads(); compute_stage(1);
    CP_WAIT(1); __syncthreads(); compute_stage(2);
    CP_WAIT(0); __syncthreads(); compute_stage(3);

    // ---- epilogue: per-row sum of exp(v - SHIFT), one atomic per row ----
    const bool edge = (c0 + 128 > C_SZ);
    float es[4][2];
    #pragma unroll
    for (int mt = 0; mt < 4; mt++) { es[mt][0] = 0.f; es[mt][1] = 0.f; }
    #pragma unroll
    for (int mt = 0; mt < 4; mt++)
        #pragma unroll
        for (int nt = 0; nt < 8; nt++) {
            int cgb = c0 + wn * 64 + nt * 8 + (lane & 3) * 2;
            #pragma unroll
            for (int h = 0; h < 2; h++) {
                float2 v = __half22float2(*(__half2*)&acc[mt][nt][h]);
                float t0 = __expf(v.x - SHIFT);
                float t1 = __expf(v.y - SHIFT);
                if (edge && (cgb + 0 >= C_SZ)) t0 = 0.f;
                if (edge && (cgb + 1 >= C_SZ)) t1 = 0.f;
                es[mt][h] += t0 + t1;
            }
        }
    #pragma unroll
    for (int m = 1; m <= 2; m <<= 1)
        #pragma unroll
        for (int mt = 0; mt < 4; mt++) {
            es[mt][0] += __shfl_xor_sync(0xffffffffu, es[mt][0], m);
            es[mt][1] += __shfl_xor_sync(0xffffffffu, es[mt][1], m);
        }

    float* rbuf = (float*)(smem + RBUF_OFF);          // [2 wm][2 wn][64 rows]
    if ((lane & 3) == 0) {
        int rl = lane >> 2;
        #pragma unroll
        for (int mt = 0; mt < 4; mt++) {
            rbuf[(wm * 2 + wn) * 64 + mt * 16 + rl]     = es[mt][0];
            rbuf[(wm * 2 + wn) * 64 + mt * 16 + 8 + rl] = es[mt][1];
        }
    }
    __syncthreads();
    {
        int wmx = tid >> 6, rl = tid & 63;
        float s = rbuf[(wmx * 2 + 0) * 64 + rl] + rbuf[(wmx * 2 + 1) * 64 + rl];
        atomicAdd(&g_rowsum[b0 + tid], s);            // RED.ADD, 512 addrs, low contention
    }
}

// ---------------- kernel 3: final — per-row loss + mean (1 block) ----------------
__global__ void final_kernel(const float* __restrict__ lamp, float* __restrict__ out) {
    int b = threadIdx.x;     // 512
    float lam = *lamp;

    float S0 = g_rowsum[b];
    float sv[4], svraw[4];
    int sidx[4];
    #pragma unroll
    for (int q = 0; q < 4; q++) {
        sv[q]    = g_sv[b * 4 + q];
        svraw[q] = g_svraw[b * 4 + q];
        sidx[q]  = g_sidx[b * 4 + q];
    }
    #pragma unroll
    for (int q = 0; q < 3; q++) {
        bool lastq = true;
        #pragma unroll
        for (int r = q + 1; r < 4; r++) if (sidx[r] == sidx[q]) lastq = false;
        if (lastq) S0 += __expf(sv[q] - SHIFT) - __expf(svraw[q] - SHIFT);
    }
    S0 += __expf(sv[3] - SHIFT) - __expf(svraw[3] - SHIFT);
    float lz = SHIFT + logf(S0);
    float l = lam * (0.2f * (lz - sv[0]) + 0.8f * (lz - sv[1]))
            + (1.f - lam) * (0.2f * (lz - sv[2]) + 0.8f * (lz - sv[3]));

    __shared__ float red[512];
    red[b] = l;
    __syncthreads();
    for (int st = 256; st; st >>= 1) {
        if (b < st) red[b] += red[b + st];
        __syncthreads();
    }
    if (b == 0) out[0] = red[0] / (float)B_SZ;
}

// ---------------- host launch ----------------
extern "C" void kernel_launch(void* const* d_in, const int* in_sizes, int n_in,
                              void* d_out, int out_size) {
    const float* x   = (const float*)d_in[0];
    const float* w   = (const float*)d_in[1];
    const float* lam = (const float*)d_in[2];
    const int* t1    = (const int*)d_in[3];
    const int* p1    = (const int*)d_in[4];
    const int* t2    = (const int*)d_in[5];
    const int* p2    = (const int*)d_in[6];
    float* out = (float*)d_out;

    static bool attr_set = false;
    if (!attr_set) {
        cudaFuncSetAttribute(gemm_lse_kernel,
                             cudaFuncAttributeMaxDynamicSharedMemorySize, GEMM_SMEM);
        attr_set = true;
    }

    prep_kernel<<<PREP_BLOCKS, 256>>>(w, x, t1, p1, t2, p2);
    gemm_lse_kernel<<<dim3(4, NCHB), 128, GEMM_SMEM>>>();
    final_kernel<<<1, 512>>>(lam, out);
}